// round 1
// baseline (speedup 1.0000x reference)
#include <cuda_runtime.h>
#include <cstdint>

#define EPS 1e-6f
#define IMG_H 512
#define IMG_W 512
#define PLANES 64            // B*C = 4*16
#define PX_PER_THREAD 4
#define THREADS_X (IMG_W / PX_PER_THREAD)   // 128
#define ROWS_PER_BLOCK 2

__constant__ float kINV9  = 1.0f / 9.0f;
__constant__ float kINV8  = 0.125f;

__global__ __launch_bounds__(THREADS_X * ROWS_PER_BLOCK)
void texture_martingale_kernel(const float* __restrict__ x,
                               float* __restrict__ out) {
    const int plane = blockIdx.y;                       // 0..63 (b*16+c)
    const int y     = blockIdx.x * ROWS_PER_BLOCK + threadIdx.y;
    const int x0    = threadIdx.x * PX_PER_THREAD;

    const float* __restrict__ in = x + (size_t)plane * (IMG_H * IMG_W);

    // Load 3 rows x 6 cols (zero pad out-of-range). v[r][0]=x0-1 .. v[r][5]=x0+4
    float v[3][6];
#pragma unroll
    for (int r = 0; r < 3; ++r) {
        const int yy = y + r - 1;
        if (yy < 0 || yy >= IMG_H) {
#pragma unroll
            for (int j = 0; j < 6; ++j) v[r][j] = 0.0f;
        } else {
            const float* __restrict__ row = in + yy * IMG_W;
            const float4 m = *reinterpret_cast<const float4*>(row + x0);
            v[r][1] = m.x; v[r][2] = m.y; v[r][3] = m.z; v[r][4] = m.w;
            v[r][0] = (x0 > 0)                  ? __ldg(row + x0 - 1) : 0.0f;
            v[r][5] = (x0 + PX_PER_THREAD < IMG_W) ? __ldg(row + x0 + 4) : 0.0f;
        }
    }

    // Vertical (column) partial sums over 3 rows, for 6 columns.
    float c1[6], c2[6], cp[6];
#pragma unroll
    for (int j = 0; j < 6; ++j) {
        const float a = v[0][j], b = v[1][j], c = v[2][j];
        c1[j] = a + b + c;
        c2[j] = fmaf(a, a, fmaf(b, b, c * c));
        // x * ln(x + eps); padded zeros contribute exactly 0.
        cp[j] = a * __logf(a + EPS) + b * __logf(b + EPS) + c * __logf(c + EPS);
    }

    float ocon[PX_PER_THREAD], oen[PX_PER_THREAD], oent[PX_PER_THREAD], ohom[PX_PER_THREAD];

#pragma unroll
    for (int i = 0; i < PX_PER_THREAD; ++i) {
        const float S1 = c1[i] + c1[i + 1] + c1[i + 2];
        const float S2 = c2[i] + c2[i + 1] + c2[i + 2];
        const float Sp = cp[i] + cp[i + 1] + cp[i + 2];

        const float mean = S1 * kINV9;
        // sum of squared deviations: S2 - S1*mean (== S2 - S1^2/9)
        const float vnum = fmaxf(fmaf(-S1, mean, S2), 0.0f);
        const float sd   = __fsqrt_rn(vnum * kINV8) + EPS;     // unbiased std + eps

        const float contrast = __fdividef(vnum * kINV9, sd * sd);
        const float energy   = S2 * kINV9;
        const float entropy  = -Sp * kINV9;

        float sab = 0.0f;
#pragma unroll
        for (int r = 0; r < 3; ++r)
#pragma unroll
            for (int j = 0; j < 3; ++j)
                sab += fabsf(v[r][i + j] - mean);
        const float hom = __frcp_rn(fmaf(sab, kINV9, 1.0f));

        const float EXPM = 0.60653065971263342f;  // exp(-0.5), theta=1
        ocon[i] = (contrast + EPS) * EXPM;
        oen[i]  = (energy   + EPS) * EXPM;
        oent[i] = (entropy  + EPS) * EXPM;
        ohom[i] = (hom      + EPS) * EXPM;
    }

    // out plane for (plane, feature f) = 4*plane + f ;  4 coalesced float4 stores
    const size_t rowoff = (size_t)y * IMG_W + x0;
    const size_t planeSz = (size_t)IMG_H * IMG_W;
    float* __restrict__ o0 = out + (size_t)(4 * plane + 0) * planeSz + rowoff;
    float* __restrict__ o1 = out + (size_t)(4 * plane + 1) * planeSz + rowoff;
    float* __restrict__ o2 = out + (size_t)(4 * plane + 2) * planeSz + rowoff;
    float* __restrict__ o3 = out + (size_t)(4 * plane + 3) * planeSz + rowoff;

    *reinterpret_cast<float4*>(o0) = make_float4(ocon[0], ocon[1], ocon[2], ocon[3]);
    *reinterpret_cast<float4*>(o1) = make_float4(oen[0],  oen[1],  oen[2],  oen[3]);
    *reinterpret_cast<float4*>(o2) = make_float4(oent[0], oent[1], oent[2], oent[3]);
    *reinterpret_cast<float4*>(o3) = make_float4(ohom[0], ohom[1], ohom[2], ohom[3]);
}

extern "C" void kernel_launch(void* const* d_in, const int* in_sizes, int n_in,
                              void* d_out, int out_size) {
    const float* x = (const float*)d_in[0];
    float* out = (float*)d_out;

    dim3 block(THREADS_X, ROWS_PER_BLOCK);
    dim3 grid(IMG_H / ROWS_PER_BLOCK, PLANES);
    texture_martingale_kernel<<<grid, block>>>(x, out);
}

// round 2
// speedup vs baseline: 1.1039x; 1.1039x over previous
#include <cuda_runtime.h>
#include <cstdint>

#define EPS      1e-6f
#define IMG_H    512
#define IMG_W    512
#define PLANES   64            // B*C = 4*16
#define PX       4             // pixels per thread in x
#define TX       (IMG_W / PX)  // 128 threads
#define ROWS_OUT 8             // output rows per thread (vertical streaming)

// exp(-0.5) and folded constants
#define EXPM     0.60653065971263342f
#define EXPM_9   (EXPM / 9.0f)
#define EPS_EXPM (EPS * EXPM)

// Load one input row segment: 4 interior cols via float4 + 2 halo scalars.
// Also compute p = x*ln(x+eps) per element (done once per loaded row).
__device__ __forceinline__ void load_row(const float* __restrict__ base,
                                         int x0, bool valid,
                                         float v[6], float p[6]) {
    if (valid) {
        const float4 m = *reinterpret_cast<const float4*>(base + x0);
        v[1] = m.x; v[2] = m.y; v[3] = m.z; v[4] = m.w;
        v[0] = (x0 > 0)            ? __ldg(base + x0 - 1)  : 0.0f;
        v[5] = (x0 + PX < IMG_W)   ? __ldg(base + x0 + PX) : 0.0f;
    } else {
#pragma unroll
        for (int j = 0; j < 6; ++j) v[j] = 0.0f;
    }
#pragma unroll
    for (int j = 0; j < 6; ++j) p[j] = v[j] * __logf(v[j] + EPS);
}

__global__ __launch_bounds__(TX)
void texture_martingale_kernel(const float* __restrict__ x,
                               float* __restrict__ out) {
    const int plane = blockIdx.y;                   // 0..63 (b*16+c)
    const int y0    = blockIdx.x * ROWS_OUT;
    const int x0    = threadIdx.x * PX;

    const float* __restrict__ in = x + (size_t)plane * (IMG_H * IMG_W);

    // 3-row ring of raw values + precomputed x*ln(x+eps)
    float v[3][6], p[3][6];
    load_row(in + (y0 - 1) * IMG_W, x0, y0 > 0, v[0], p[0]);
    load_row(in +  y0      * IMG_W, x0, true,   v[1], p[1]);

    const size_t planeSz = (size_t)IMG_H * IMG_W;
    float* __restrict__ o0 = out + (size_t)(4 * plane) * planeSz
                                 + (size_t)y0 * IMG_W + x0;
    float* __restrict__ o1 = o0 + planeSz;
    float* __restrict__ o2 = o0 + 2 * planeSz;
    float* __restrict__ o3 = o0 + 3 * planeSz;

#pragma unroll
    for (int r = 0; r < ROWS_OUT; ++r) {
        const int sa = r % 3, sb = (r + 1) % 3, sc = (r + 2) % 3;
        const int yy = y0 + r + 1;
        load_row(in + yy * IMG_W, x0, yy < IMG_H, v[sc], p[sc]);

        // Vertical column sums over the 3-row window, 6 columns.
        float c1[6], c2[6], cp[6];
#pragma unroll
        for (int j = 0; j < 6; ++j) {
            const float a = v[sa][j], b = v[sb][j], c = v[sc][j];
            c1[j] = a + b + c;
            c2[j] = fmaf(a, a, fmaf(b, b, c * c));
            cp[j] = p[sa][j] + p[sb][j] + p[sc][j];
        }

        float oc[PX], oe[PX], ot[PX], oh[PX];
#pragma unroll
        for (int i = 0; i < PX; ++i) {
            const float S1 = c1[i] + c1[i + 1] + c1[i + 2];
            const float S2 = c2[i] + c2[i + 1] + c2[i + 2];
            const float Sp = cp[i] + cp[i + 1] + cp[i + 2];

            const float mean = S1 * (1.0f / 9.0f);
            const float vnum = fmaxf(fmaf(-S1, mean, S2), 0.0f);   // sum (x-mu)^2
            const float sd   = __fsqrt_rn(vnum * 0.125f) + EPS;    // unbiased std + eps

            // contrast*EXPM folded into numerator
            const float con = __fdividef(vnum * EXPM_9, sd * sd);

            float sab = 0.0f;
#pragma unroll
            for (int jj = 0; jj < 3; ++jj) {
                sab += fabsf(v[sa][i + jj] - mean);
                sab += fabsf(v[sb][i + jj] - mean);
                sab += fabsf(v[sc][i + jj] - mean);
            }
            const float hom = __frcp_rn(fmaf(sab, 1.0f / 9.0f, 1.0f));

            oc[i] = con + EPS_EXPM;
            oe[i] = fmaf(S2,  EXPM_9,  EPS_EXPM);   // energy
            ot[i] = fmaf(Sp, -EXPM_9,  EPS_EXPM);   // entropy
            oh[i] = fmaf(hom, EXPM,    EPS_EXPM);   // homogeneity
        }

        *reinterpret_cast<float4*>(o0) = make_float4(oc[0], oc[1], oc[2], oc[3]);
        *reinterpret_cast<float4*>(o1) = make_float4(oe[0], oe[1], oe[2], oe[3]);
        *reinterpret_cast<float4*>(o2) = make_float4(ot[0], ot[1], ot[2], ot[3]);
        *reinterpret_cast<float4*>(o3) = make_float4(oh[0], oh[1], oh[2], oh[3]);
        o0 += IMG_W; o1 += IMG_W; o2 += IMG_W; o3 += IMG_W;
    }
}

extern "C" void kernel_launch(void* const* d_in, const int* in_sizes, int n_in,
                              void* d_out, int out_size) {
    const float* x = (const float*)d_in[0];
    float* out = (float*)d_out;

    dim3 block(TX, 1);
    dim3 grid(IMG_H / ROWS_OUT, PLANES);
    texture_martingale_kernel<<<grid, block>>>(x, out);
}

// round 3
// speedup vs baseline: 1.2869x; 1.1658x over previous
#include <cuda_runtime.h>
#include <cstdint>

#define EPS      1e-6f
#define IMG_H    512
#define IMG_W    512
#define PLANES   64            // B*C = 4*16
#define PX       4             // pixels per thread in x
#define TX       (IMG_W / PX)  // 128 threads
#define ROWS_OUT 8             // output rows per thread

#define EXPM     0.60653065971263342f   // exp(-0.5), theta=1
#define EXPM_9   (EXPM / 9.0f)
#define EPS_EXPM (EPS * EXPM)

__device__ __forceinline__ float fsqrt_approx(float a) {
    float r; asm("sqrt.approx.f32 %0, %1;" : "=f"(r) : "f"(a)); return r;
}
__device__ __forceinline__ float frcp_approx(float a) {
    float r; asm("rcp.approx.f32 %0, %1;" : "=f"(r) : "f"(a)); return r;
}

// Raw load only (no math) so LDGs can be issued far ahead of use.
__device__ __forceinline__ void load_raw(const float* __restrict__ base,
                                         int x0, bool valid, float w[6]) {
    if (valid) {
        const float4 m = *reinterpret_cast<const float4*>(base + x0);
        w[1] = m.x; w[2] = m.y; w[3] = m.z; w[4] = m.w;
        w[0] = (x0 > 0)          ? __ldg(base + x0 - 1)  : 0.0f;
        w[5] = (x0 + PX < IMG_W) ? __ldg(base + x0 + PX) : 0.0f;
    } else {
#pragma unroll
        for (int j = 0; j < 6; ++j) w[j] = 0.0f;
    }
}

__global__ __launch_bounds__(TX)
void texture_martingale_kernel(const float* __restrict__ x,
                               float* __restrict__ out) {
    const int plane = blockIdx.y;                   // 0..63 (b*16+c)
    const int y0    = blockIdx.x * ROWS_OUT;
    const int x0    = threadIdx.x * PX;

    const float* __restrict__ in = x + (size_t)plane * (IMG_H * IMG_W);

    // 3-row ring (values + x*ln(x+eps)) and a raw prefetch row.
    float v[3][6], p[3][6], nx[6];
    load_raw(in + (y0 - 1) * IMG_W, x0, y0 > 0, v[0]);
    load_raw(in +  y0      * IMG_W, x0, true,   v[1]);
    load_raw(in + (y0 + 1) * IMG_W, x0, true,   nx);   // y0+1 <= 505 always valid
#pragma unroll
    for (int j = 0; j < 6; ++j) {
        p[0][j] = v[0][j] * __logf(v[0][j] + EPS);
        p[1][j] = v[1][j] * __logf(v[1][j] + EPS);
    }

    const size_t planeSz = (size_t)IMG_H * IMG_W;
    float* __restrict__ o0 = out + (size_t)(4 * plane) * planeSz
                                 + (size_t)y0 * IMG_W + x0;
    float* __restrict__ o1 = o0 + planeSz;
    float* __restrict__ o2 = o0 + 2 * planeSz;
    float* __restrict__ o3 = o0 + 3 * planeSz;

#pragma unroll
    for (int r = 0; r < ROWS_OUT; ++r) {
        const int sa = r % 3, sb = (r + 1) % 3, sc = (r + 2) % 3;

        // Commit prefetched row into the ring (renamed away by full unroll).
#pragma unroll
        for (int j = 0; j < 6; ++j) v[sc][j] = nx[j];

        // Issue next row's LDGs NOW; consumed only next iteration.
        const int yy = y0 + r + 2;
        load_raw(in + yy * IMG_W, x0, yy < IMG_H, nx);

        // Convert committed row (once per loaded row).
#pragma unroll
        for (int j = 0; j < 6; ++j)
            p[sc][j] = v[sc][j] * __logf(v[sc][j] + EPS);

        // Vertical column sums over the 3-row window, 6 columns.
        float c1[6], c2[6], cp[6];
#pragma unroll
        for (int j = 0; j < 6; ++j) {
            const float a = v[sa][j], b = v[sb][j], c = v[sc][j];
            c1[j] = a + b + c;
            c2[j] = fmaf(a, a, fmaf(b, b, c * c));
            cp[j] = p[sa][j] + p[sb][j] + p[sc][j];
        }

        float oc[PX], oe[PX], ot[PX], oh[PX];
#pragma unroll
        for (int i = 0; i < PX; ++i) {
            const float S1 = c1[i] + c1[i + 1] + c1[i + 2];
            const float S2 = c2[i] + c2[i + 1] + c2[i + 2];
            const float Sp = cp[i] + cp[i + 1] + cp[i + 2];

            const float mean = S1 * (1.0f / 9.0f);
            const float vnum = fmaxf(fmaf(-S1, mean, S2), 0.0f);   // sum (x-mu)^2
            const float sd   = fsqrt_approx(vnum * 0.125f) + EPS;  // unbiased std + eps
            const float rden = frcp_approx(sd * sd);

            float sab = 0.0f;
#pragma unroll
            for (int jj = 0; jj < 3; ++jj) {
                sab += fabsf(v[sa][i + jj] - mean);
                sab += fabsf(v[sb][i + jj] - mean);
                sab += fabsf(v[sc][i + jj] - mean);
            }
            const float hom = frcp_approx(fmaf(sab, 1.0f / 9.0f, 1.0f));

            oc[i] = fmaf(vnum * EXPM_9, rden, EPS_EXPM);   // contrast
            oe[i] = fmaf(S2,  EXPM_9,  EPS_EXPM);          // energy
            ot[i] = fmaf(Sp, -EXPM_9,  EPS_EXPM);          // entropy
            oh[i] = fmaf(hom, EXPM,    EPS_EXPM);          // homogeneity
        }

        *reinterpret_cast<float4*>(o0) = make_float4(oc[0], oc[1], oc[2], oc[3]);
        *reinterpret_cast<float4*>(o1) = make_float4(oe[0], oe[1], oe[2], oe[3]);
        *reinterpret_cast<float4*>(o2) = make_float4(ot[0], ot[1], ot[2], ot[3]);
        *reinterpret_cast<float4*>(o3) = make_float4(oh[0], oh[1], oh[2], oh[3]);
        o0 += IMG_W; o1 += IMG_W; o2 += IMG_W; o3 += IMG_W;
    }
}

extern "C" void kernel_launch(void* const* d_in, const int* in_sizes, int n_in,
                              void* d_out, int out_size) {
    const float* x = (const float*)d_in[0];
    float* out = (float*)d_out;

    dim3 block(TX, 1);
    dim3 grid(IMG_H / ROWS_OUT, PLANES);
    texture_martingale_kernel<<<grid, block>>>(x, out);
}